// round 12
// baseline (speedup 1.0000x reference)
#include <cuda_runtime.h>
#include <cuda.h>
#include <cstdint>
#include <cstddef>

#define IN_F   4096
#define OUT_F  11008
#define BATCH  32
#define N_TILE 64
#define K_TILE 64
#define K_SPLIT 4
#define STAGES 4
#define THREADS 128
#define NTILES_K 64                  // total k-tiles
#define NITER_U (NTILES_K / K_SPLIT) // 16 iters per unit
#define N_UNITS ((OUT_F / N_TILE) * K_SPLIT)   // 688

// X fragment-packed layout: [tile][ksw][lane][t][16B], lane stride 80B.
#define XSTAGE  5120
#define WSTAGE  (N_TILE * K_TILE * 4)        // 16384 B
#define DSM_W   (STAGES * WSTAGE)            // 65536
#define DSM_X   (STAGES * XSTAGE)            // 20480
#define DSM_TOTAL (DSM_W + DSM_X)            // 86016
#define TX_BYTES (WSTAGE + XSTAGE)           // 21504 per stage

__device__ __align__(128) signed char g_xq[NTILES_K * XSTAGE];
// Partials: [kseg][m 32][n*2 (plane-interleaved)] int32, each slot written once.
__device__ __align__(16) int g_part[K_SPLIT][BATCH][OUT_F * 2];

__global__ void quantize_x_kernel(const float* __restrict__ x) {
    int i = blockIdx.x * blockDim.x + threadIdx.x;      // i = b*4096 + k
    if (i >= BATCH * IN_F) return;
    int b = i >> 12, k = i & 4095;
    float v  = x[i];
    float q1 = rintf(v * 16.0f);
    q1 = fminf(fmaxf(q1, -127.0f), 127.0f);
    float r  = v - q1 * 0.0625f;
    float q2 = rintf(r * 4096.0f);
    q2 = fminf(fmaxf(q2, -127.0f), 127.0f);

    int tile = k >> 6, kl = k & 63;
    int ksw  = kl >> 5, rem = kl & 31;
    int o    = rem & 3;
    int q    = (rem >> 2) & 3;
    int hi16 = rem >> 4;
    int g    = b & 7;
    int rl   = (b >> 3) & 1;
    int th   = b >> 4;
    int j    = (rl + 2 * hi16) * 4 + o;
    int lane = g * 4 + q;

    signed char* base = g_xq + tile * XSTAGE + ksw * 2560 + lane * 80 + j;
    base[th * 16]       = (signed char)(int)q1;
    base[(th + 2) * 16] = (signed char)(int)q2;
}

__device__ __forceinline__ uint32_t smem_u32(const void* p) {
    return (uint32_t)__cvta_generic_to_shared(p);
}
__device__ __forceinline__ void mbar_init(uint32_t bar, uint32_t cnt) {
    asm volatile("mbarrier.init.shared.b64 [%0], %1;" :: "r"(bar), "r"(cnt) : "memory");
}
__device__ __forceinline__ void mbar_expect_tx(uint32_t bar, uint32_t bytes) {
    asm volatile("mbarrier.arrive.expect_tx.shared.b64 _, [%0], %1;"
                 :: "r"(bar), "r"(bytes) : "memory");
}
__device__ __forceinline__ void tma_load_2d(uint32_t sdst, const CUtensorMap* map,
                                            int cx, int cy, uint32_t bar) {
    asm volatile(
        "cp.async.bulk.tensor.2d.shared::cta.global.tile.mbarrier::complete_tx::bytes "
        "[%0], [%1, {%2, %3}], [%4];"
        :: "r"(sdst), "l"(map), "r"(cx), "r"(cy), "r"(bar) : "memory");
}
__device__ __forceinline__ void mbar_wait(uint32_t bar, uint32_t parity) {
    uint32_t done;
    asm volatile(
        "{\n\t.reg .pred p;\n\t"
        "mbarrier.try_wait.parity.acquire.cta.shared::cta.b64 p, [%1], %2;\n\t"
        "selp.b32 %0, 1, 0, p;\n\t}"
        : "=r"(done) : "r"(bar), "r"(parity) : "memory");
    if (!done) {
        asm volatile(
            "{\n\t.reg .pred P1;\n\t"
            "WAIT_LOOP_%=:\n\t"
            "mbarrier.try_wait.parity.acquire.cta.shared::cta.b64 P1, [%0], %1, 0x989680;\n\t"
            "@P1 bra.uni WAIT_DONE_%=;\n\t"
            "bra.uni WAIT_LOOP_%=;\n\t"
            "WAIT_DONE_%=:\n\t}"
            :: "r"(bar), "r"(parity) : "memory");
    }
}
__device__ __forceinline__ void mma_s8(int d[4], const int a[4], const int b[2]) {
    asm volatile(
        "mma.sync.aligned.m16n8k32.row.col.s32.s8.s8.s32 "
        "{%0,%1,%2,%3}, {%4,%5,%6,%7}, {%8,%9}, {%0,%1,%2,%3};"
        : "+r"(d[0]), "+r"(d[1]), "+r"(d[2]), "+r"(d[3])
        : "r"(a[0]), "r"(a[1]), "r"(a[2]), "r"(a[3]), "r"(b[0]), "r"(b[1]));
}

// One unit = (n-tile of 64 rows) x (k-segment of 1024). Writes int32 partials.
__global__ __launch_bounds__(THREADS, 2)
void qlinear_gemm_tma(const __grid_constant__ CUtensorMap tmap_w,
                      const __grid_constant__ CUtensorMap tmap_x,
                      const float* __restrict__ scale_p) {
    extern __shared__ __align__(128) char dsm[];
    char* wsm = dsm;            // [STAGES][64 rows][256B]
    char* xsm = dsm + DSM_W;    // [STAGES][2][32][80B]
    __shared__ __align__(8) unsigned long long mbar_store[STAGES];

    const int tid  = threadIdx.x;
    const int u    = blockIdx.x;
    const int kseg = u & (K_SPLIT - 1);
    const int n0   = (u >> 2) * N_TILE;
    const int lane = tid & 31;
    const int warp = tid >> 5;
    const int ksw  = warp & 1;       // k-slice within tile
    const int nh   = warp >> 1;      // n-half: cols [nh*32, nh*32+32)
    const int g    = lane >> 2;
    const int q    = lane & 3;
    const uint32_t mbar0 = smem_u32(mbar_store);

    if (tid == 0) {
        #pragma unroll
        for (int s = 0; s < STAGES; ++s) mbar_init(mbar0 + 8u * s, 1);
    }
    __syncthreads();

    const int ktile0 = kseg * NITER_U;
    if (tid == 0) {
        #pragma unroll
        for (int s = 0; s < STAGES - 1; ++s) {
            mbar_expect_tx(mbar0 + 8u * s, TX_BYTES);
            tma_load_2d(smem_u32(wsm) + s * WSTAGE, &tmap_w, (ktile0 + s) * K_TILE, n0, mbar0 + 8u * s);
            tma_load_2d(smem_u32(xsm) + s * XSTAGE, &tmap_x, 0, (ktile0 + s) * 64, mbar0 + 8u * s);
        }
    }

    int acc[4][4][4];   // [m_tile(t: 0..1 q1, 2..3 q2)][n_frag][reg]
    #pragma unroll
    for (int t = 0; t < 4; ++t)
        #pragma unroll
        for (int f = 0; f < 4; ++f)
            #pragma unroll
            for (int r = 0; r < 4; ++r) acc[t][f][r] = 0;

    const int xoff = ksw * 2560 + lane * 80;

    for (int it = 0; it < NITER_U; ++it) {
        const int s = it & (STAGES - 1);
        mbar_wait(mbar0 + 8u * s, (it >> 2) & 1);
        __syncthreads();

        const int pf = it + STAGES - 1;
        if (tid == 0 && pf < NITER_U) {
            const int b = pf & (STAGES - 1);
            mbar_expect_tx(mbar0 + 8u * b, TX_BYTES);
            tma_load_2d(smem_u32(wsm) + b * WSTAGE, &tmap_w, (ktile0 + pf) * K_TILE, n0, mbar0 + 8u * b);
            tma_load_2d(smem_u32(xsm) + b * XSTAGE, &tmap_x, 0, (ktile0 + pf) * 64, mbar0 + 8u * b);
        }

        const char* wst = wsm + s * WSTAGE;
        const char* xfr = xsm + s * XSTAGE + xoff;

        int a[4][4];
        #pragma unroll
        for (int t = 0; t < 4; ++t)
            *(int4*)a[t] = *(const int4*)(xfr + t * 16);

        #pragma unroll
        for (int f = 0; f < 4; ++f) {
            const int nloc = nh * 32 + f * 8 + g;
            const char* wr = wst + nloc * 256 + ksw * 128 + q * 16;
            const int4 w0 = *(const int4*)wr;
            const int4 w1 = *(const int4*)(wr + 64);
            int b[2];
            b[0] = __byte_perm(__byte_perm(w0.x, w0.y, 0x0040),
                               __byte_perm(w0.z, w0.w, 0x0040), 0x5410);
            b[1] = __byte_perm(__byte_perm(w1.x, w1.y, 0x0040),
                               __byte_perm(w1.z, w1.w, 0x0040), 0x5410);
            #pragma unroll
            for (int t = 0; t < 4; ++t)
                mma_s8(acc[t][f], a[t], b);
        }
    }

    // In-CTA ksw reduction through smem scratch (ring is drained; reuse it).
    __syncthreads();
    int4* scratch = (int4*)(dsm + nh * 8192);
    if (ksw == 1) {
        #pragma unroll
        for (int t = 0; t < 4; ++t)
            #pragma unroll
            for (int f = 0; f < 4; ++f)
                scratch[(t * 4 + f) * 32 + lane] =
                    make_int4(acc[t][f][0], acc[t][f][1], acc[t][f][2], acc[t][f][3]);
    }
    __syncthreads();
    if (ksw == 0) {
        #pragma unroll
        for (int t = 0; t < 4; ++t)
            #pragma unroll
            for (int f = 0; f < 4; ++f) {
                const int4 p = scratch[(t * 4 + f) * 32 + lane];
                acc[t][f][0] += p.x; acc[t][f][1] += p.y;
                acc[t][f][2] += p.z; acc[t][f][3] += p.w;
            }
        // Store partials: int4 = {a1[c], a2[c], a1[c+1], a2[c+1]} at (r, n=c..c+1).
        #pragma unroll
        for (int t = 0; t < 2; ++t)
            #pragma unroll
            for (int f = 0; f < 4; ++f) {
                const int n = n0 + nh * 32 + f * 8 + q * 2;
                #pragma unroll
                for (int rr = 0; rr < 2; ++rr) {
                    const int r = t * 16 + g + rr * 8;
                    int4 v = make_int4(acc[t][f][rr * 2],     acc[t + 2][f][rr * 2],
                                       acc[t][f][rr * 2 + 1], acc[t + 2][f][rr * 2 + 1]);
                    *(int4*)&g_part[kseg][r][n * 2] = v;
                }
            }
    }
}

// Sum K_SPLIT partials, apply scale & bias.
__global__ void reduce_epilogue(const float* __restrict__ scale_p,
                                const float* __restrict__ bias,
                                float* __restrict__ out) {
    int idx = blockIdx.x * blockDim.x + threadIdx.x;
    if (idx >= BATCH * OUT_F) return;
    int r = idx / OUT_F, n = idx - r * OUT_F;
    int a1 = 0, a2 = 0;
    #pragma unroll
    for (int k = 0; k < K_SPLIT; ++k) {
        int2 p = *(const int2*)&g_part[k][r][n * 2];
        a1 += p.x; a2 += p.y;
    }
    const float sc = __ldg(scale_p);
    out[idx] = fmaf(sc, fmaf(0.0625f, (float)a1, (float)a2 * (1.0f / 4096.0f)),
                    __ldg(&bias[n]));
}

typedef CUresult (*EncodeTiledFn)(
    CUtensorMap*, CUtensorMapDataType, cuuint32_t, void*,
    const cuuint64_t*, const cuuint64_t*, const cuuint32_t*, const cuuint32_t*,
    CUtensorMapInterleave, CUtensorMapSwizzle, CUtensorMapL2promotion,
    CUtensorMapFloatOOBfill);

extern "C" void kernel_launch(void* const* d_in, const int* in_sizes, int n_in,
                              void* d_out, int out_size) {
    // Bind inputs by element count (ordering-proof): all four counts are distinct.
    const float* x = nullptr; void* w = nullptr;
    const float* scale = nullptr; const float* bias = nullptr;
    for (int i = 0; i < n_in; ++i) {
        switch (in_sizes[i]) {
            case BATCH * IN_F:    x     = (const float*)d_in[i]; break;
            case OUT_F * IN_F:    w     = (void*)d_in[i];        break;
            case 1:               scale = (const float*)d_in[i]; break;
            case OUT_F:           bias  = (const float*)d_in[i]; break;
        }
    }
    float* out = (float*)d_out;

    static EncodeTiledFn encode_fn = nullptr;
    static bool attr_done = false;
    if (!encode_fn) {
        cudaDriverEntryPointQueryResult qr;
        void* fp = nullptr;
        cudaGetDriverEntryPoint("cuTensorMapEncodeTiled", &fp,
                                cudaEnableDefault, &qr);
        encode_fn = (EncodeTiledFn)fp;
    }
    if (!attr_done) {
        cudaFuncSetAttribute(qlinear_gemm_tma,
                             cudaFuncAttributeMaxDynamicSharedMemorySize, DSM_TOTAL);
        attr_done = true;
    }

    // W map: uint32 words, dims [IN_F, OUT_F], box [K_TILE=64, N_TILE=64].
    CUtensorMap tmap_w;
    {
        cuuint64_t dims[2]    = {IN_F, OUT_F};
        cuuint64_t strides[1] = {IN_F * sizeof(int)};
        cuuint32_t box[2]     = {K_TILE, N_TILE};
        cuuint32_t estr[2]    = {1, 1};
        encode_fn(&tmap_w, CU_TENSOR_MAP_DATA_TYPE_UINT32, 2, w,
                  dims, strides, box, estr,
                  CU_TENSOR_MAP_INTERLEAVE_NONE, CU_TENSOR_MAP_SWIZZLE_NONE,
                  CU_TENSOR_MAP_L2_PROMOTION_L2_128B, CU_TENSOR_MAP_FLOAT_OOB_FILL_NONE);
    }
    // X map over g_xq: rows of 80B (20 words), 64 rows per k-tile.
    CUtensorMap tmap_x;
    {
        void* xq_dev = nullptr;
        cudaGetSymbolAddress(&xq_dev, g_xq);
        cuuint64_t dims[2]    = {20, (cuuint64_t)NTILES_K * 64};
        cuuint64_t strides[1] = {80};
        cuuint32_t box[2]     = {20, 64};
        cuuint32_t estr[2]    = {1, 1};
        encode_fn(&tmap_x, CU_TENSOR_MAP_DATA_TYPE_UINT32, 2, xq_dev,
                  dims, strides, box, estr,
                  CU_TENSOR_MAP_INTERLEAVE_NONE, CU_TENSOR_MAP_SWIZZLE_NONE,
                  CU_TENSOR_MAP_L2_PROMOTION_L2_128B, CU_TENSOR_MAP_FLOAT_OOB_FILL_NONE);
    }

    quantize_x_kernel<<<(BATCH * IN_F + 255) / 256, 256>>>(x);
    qlinear_gemm_tma<<<N_UNITS, THREADS, DSM_TOTAL>>>(tmap_w, tmap_x, scale);
    reduce_epilogue<<<(BATCH * OUT_F + 255) / 256, 256>>>(scale, bias, out);
}